// round 10
// baseline (speedup 1.0000x reference)
#include <cuda_runtime.h>
#include <math.h>
#include <stddef.h>

// Problem constants
#define MV   128      // sequence length M
#define BV   32       // batch
#define HV   256      // hidden == embed dim
#define VV   4000     // vocab
#define SV   126      // M-2 segment starts
#define NBV  4032     // S*B decoder batch
#define NROW 20160    // 5 * NBV logits rows
#define NCB  63       // ceil(4000/64) column blocks in logits GEMM
#define NEGBIG (-1e6f)
#define ENCBLK 128

typedef unsigned long long ull;

__device__ __forceinline__ ull ffma2(ull a, ull b, ull c){
    ull d; asm("fma.rn.f32x2 %0,%1,%2,%3;" : "=l"(d) : "l"(a), "l"(b), "l"(c)); return d;
}
__device__ __forceinline__ ull pack2(float lo, float hi){
    ull d; asm("mov.b64 %0,{%1,%2};" : "=l"(d) : "f"(lo), "f"(hi)); return d;
}
__device__ __forceinline__ float2 unpack2(ull v){
    float2 r; asm("mov.b64 {%0,%1},%2;" : "=f"(r.x), "=f"(r.y) : "l"(v)); return r;
}
__device__ __forceinline__ float sigm(float x){ return 1.f/(1.f + expf(-x)); }

// ---------------- device scratch ----------------
__device__ float g_inp[4096*256];       // embedded inputs, row = m*32+b
__device__ float g_issingle[4096];
__device__ float g_xge[4096*1024];      // encoder input-gates (incl. both biases)
__device__ float g_xgd[4160*1024];      // decoder input-gates, 130 positions x 32
__device__ float g_h[2][8192];          // encoder h, [buf][b*256+k]  (double buffered)
__device__ float g_encout[4096*256];    // 0.5*h, row m*32+b
__device__ float g_sos[4032*256];
__device__ float g_sosxg[4032*1024];
__device__ float g_dech[4032*256];
__device__ float g_decc[4032*256];
__device__ float g_gh[4032*1024];
__device__ float g_decout[5*4032*256];  // [t][s*32+b][h]
__device__ float g_pmax[NROW*NCB];
__device__ float g_psum[NROW*NCB];
__device__ float g_logZ[NROW];
__device__ float g_lt[16128];
__device__ float g_le[16128];
__device__ float g_logpy[16128];
__device__ unsigned g_barcnt;
__device__ volatile unsigned g_barflag;

// ---------------- embedding gather + is_single ----------------
__global__ void embed_kernel(const int* __restrict__ x, const float* __restrict__ emb){
    int blk = blockIdx.x;            // m*32+b
    int m = blk >> 5, b = blk & 31;
    int token = x[b*MV + m];
    g_inp[(size_t)blk*256 + threadIdx.x] = emb[(size_t)token*256 + threadIdx.x];
    if (threadIdx.x == 0)
        g_issingle[blk] = ((unsigned)token <= 2u) ? NEGBIG : 0.f;
}

// ---------------- init: h0 broadcast, decoder pad-row gates, barrier reset ------
__global__ void init_state(const float* __restrict__ h0,
                           const float* __restrict__ dbih, const float* __restrict__ dbhh){
    int idx = blockIdx.x*256 + threadIdx.x;   // 288*256 = 73728
    if (idx < 8192){
        g_h[0][idx] = h0[idx & 255];
    } else if (idx < 8192 + 65536){
        int j = idx - 8192;                   // pad positions 128,129
        int n = j & 1023;
        g_xgd[(size_t)4096*1024 + j] = dbih[n] + dbhh[n];
    }
    if (idx == 0){ g_barcnt = 0; g_barflag = 0; }
}

// ======== fp32x2 GEMM core: C[R][N] = A[R][256] @ W[N][256]^T (+b0+b1, opt tanh) ====
// 256 threads, tile 128 rows x 64 cols, acc = 4 row-pairs x 4 cols (ull each)
#define GEMM_BODY(RR, NN) \
    __shared__ __align__(16) float As[16][128]; \
    __shared__ __align__(16) ull  Bsd[16][64]; \
    int tid = threadIdx.x; \
    int r0 = blockIdx.x*128, n0 = blockIdx.y*64; \
    int ty = tid >> 4, tx = tid & 15; \
    ull accp[4][4]; \
    _Pragma("unroll") for (int p=0;p<4;p++) _Pragma("unroll") for (int j=0;j<4;j++) accp[p][j]=0ull; \
    int srow = tid & 63, skq = (tid >> 6)*4; \
    for (int kk=0; kk<256; kk+=16){ \
        _Pragma("unroll") \
        for (int i=0;i<2;i++){ \
            int rr = srow + i*64; \
            int ra = min(r0 + rr, (RR)-1); \
            float4 v = *(const float4*)&A[(size_t)ra*256 + kk + skq]; \
            As[skq+0][rr]=v.x; As[skq+1][rr]=v.y; As[skq+2][rr]=v.z; As[skq+3][rr]=v.w; \
        } \
        { \
            int na = min(n0 + srow, (NN)-1); \
            float4 w = *(const float4*)&W[(size_t)na*256 + kk + skq]; \
            Bsd[skq+0][srow]=pack2(w.x,w.x); Bsd[skq+1][srow]=pack2(w.y,w.y); \
            Bsd[skq+2][srow]=pack2(w.z,w.z); Bsd[skq+3][srow]=pack2(w.w,w.w); \
        } \
        __syncthreads(); \
        _Pragma("unroll") \
        for (int k=0;k<16;k++){ \
            ulonglong2 a01 = *(const ulonglong2*)&As[k][ty*8]; \
            ulonglong2 a23 = *(const ulonglong2*)&As[k][ty*8+4]; \
            ulonglong2 b01 = *(const ulonglong2*)&Bsd[k][tx*4]; \
            ulonglong2 b23 = *(const ulonglong2*)&Bsd[k][tx*4+2]; \
            accp[0][0]=ffma2(a01.x,b01.x,accp[0][0]); accp[0][1]=ffma2(a01.x,b01.y,accp[0][1]); \
            accp[0][2]=ffma2(a01.x,b23.x,accp[0][2]); accp[0][3]=ffma2(a01.x,b23.y,accp[0][3]); \
            accp[1][0]=ffma2(a01.y,b01.x,accp[1][0]); accp[1][1]=ffma2(a01.y,b01.y,accp[1][1]); \
            accp[1][2]=ffma2(a01.y,b23.x,accp[1][2]); accp[1][3]=ffma2(a01.y,b23.y,accp[1][3]); \
            accp[2][0]=ffma2(a23.x,b01.x,accp[2][0]); accp[2][1]=ffma2(a23.x,b01.y,accp[2][1]); \
            accp[2][2]=ffma2(a23.x,b23.x,accp[2][2]); accp[2][3]=ffma2(a23.x,b23.y,accp[2][3]); \
            accp[3][0]=ffma2(a23.y,b01.x,accp[3][0]); accp[3][1]=ffma2(a23.y,b01.y,accp[3][1]); \
            accp[3][2]=ffma2(a23.y,b23.x,accp[3][2]); accp[3][3]=ffma2(a23.y,b23.y,accp[3][3]); \
        } \
        __syncthreads(); \
    }

__global__ void sgemm_nt(const float* __restrict__ A, const float* __restrict__ W,
                         const float* __restrict__ b0, const float* __restrict__ b1,
                         float* __restrict__ C, int R, int N, int act){
    GEMM_BODY(R, N)
    float bias[4];
    #pragma unroll
    for (int j=0;j<4;j++){
        int n = n0 + tx*4 + j;
        float v = 0.f;
        if (n < N){ if (b0) v += b0[n]; if (b1) v += b1[n]; }
        bias[j] = v;
    }
    #pragma unroll
    for (int p=0;p<4;p++){
        int rlo = r0 + ty*8 + 2*p, rhi = rlo + 1;
        #pragma unroll
        for (int j=0;j<4;j++){
            int n = n0 + tx*4 + j;
            if (n >= N) continue;
            float2 v = unpack2(accp[p][j]);
            float vlo = v.x + bias[j], vhi = v.y + bias[j];
            if (act){ vlo = tanhf(vlo); vhi = tanhf(vhi); }
            if (rlo < R) C[(size_t)rlo*N + n] = vlo;
            if (rhi < R) C[(size_t)rhi*N + n] = vhi;
        }
    }
}

// ---------------- logits GEMM with fused per-block (max, sumexp) partials ----------
__global__ void sgemm_logits(const float* __restrict__ A, const float* __restrict__ W,
                             const float* __restrict__ bias){
    GEMM_BODY(NROW, VV)
    int cb = blockIdx.y;
    float bv[4]; int nok[4];
    #pragma unroll
    for (int j=0;j<4;j++){
        int n = n0 + tx*4 + j;
        nok[j] = (n < VV);
        bv[j] = nok[j] ? bias[n] : 0.f;
    }
    #pragma unroll
    for (int p=0;p<4;p++){
        float rv[2][4];
        #pragma unroll
        for (int j=0;j<4;j++){
            float2 v = unpack2(accp[p][j]);
            rv[0][j] = nok[j] ? (v.x + bv[j]) : -1e30f;
            rv[1][j] = nok[j] ? (v.y + bv[j]) : -1e30f;
        }
        #pragma unroll
        for (int hh=0; hh<2; hh++){
            float m = fmaxf(fmaxf(rv[hh][0],rv[hh][1]), fmaxf(rv[hh][2],rv[hh][3]));
            #pragma unroll
            for (int s=1;s<16;s<<=1) m = fmaxf(m, __shfl_xor_sync(0xffffffffu, m, s));
            float ssum = __expf(rv[hh][0]-m)+__expf(rv[hh][1]-m)+__expf(rv[hh][2]-m)+__expf(rv[hh][3]-m);
            #pragma unroll
            for (int s=1;s<16;s<<=1) ssum += __shfl_xor_sync(0xffffffffu, ssum, s);
            int r = r0 + ty*8 + 2*p + hh;
            if (tx == 0 && r < NROW){
                g_pmax[(size_t)r*NCB + cb] = m;
                g_psum[(size_t)r*NCB + cb] = ssum;
            }
        }
    }
}

__global__ void reduce_logz(){
    int row = blockIdx.x*8 + (threadIdx.x >> 5);
    int lane = threadIdx.x & 31;
    if (row >= NROW) return;
    float m1 = -1e30f, s1 = 0.f, m2 = -1e30f, s2 = 0.f;
    if (lane < NCB){ m1 = g_pmax[(size_t)row*NCB + lane]; s1 = g_psum[(size_t)row*NCB + lane]; }
    if (lane + 32 < NCB){ m2 = g_pmax[(size_t)row*NCB + lane + 32]; s2 = g_psum[(size_t)row*NCB + lane + 32]; }
    float m = fmaxf(m1, m2);
    #pragma unroll
    for (int s=16;s;s>>=1) m = fmaxf(m, __shfl_xor_sync(0xffffffffu, m, s));
    float ss = s1*__expf(m1 - m) + s2*__expf(m2 - m);
    #pragma unroll
    for (int s=16;s;s>>=1) ss += __shfl_xor_sync(0xffffffffu, ss, s);
    if (lane == 0) g_logZ[row] = m + logf(ss);
}

// ---------------- persistent encoder: 128 blocks, grid barrier per step ------------
__global__ void __launch_bounds__(256, 1) enc_persist(const float* __restrict__ Whh,
                                                      const float* __restrict__ c0){
    __shared__ __align__(16) float ws[8][256];   // 8 gate-rows for this block's 2 hc
    __shared__ __align__(16) float hs[32][260];  // h staged, padded stride (1040B, 16B-aligned)
    __shared__ float gs[4][2][32];
    int tid = threadIdx.x;
    int g = tid >> 6, hcL = (tid >> 5) & 1, b = tid & 31;
    int hc = blockIdx.x*2 + hcL;
    int n = g*256 + hc;                          // gate column index 0..1023
    int rowL = g*2 + hcL;

    // stage weights once: ws[rL][k] = Whh[(rL>>1)*256 + blk*2 + (rL&1)][k]
    {
        int rL = tid >> 5; int k0 = (tid & 31)*8;
        int nr = (rL >> 1)*256 + blockIdx.x*2 + (rL & 1);
        float4 w1 = *(const float4*)&Whh[(size_t)nr*256 + k0];
        float4 w2 = *(const float4*)&Whh[(size_t)nr*256 + k0 + 4];
        *(float4*)&ws[rL][k0] = w1; *(float4*)&ws[rL][k0+4] = w2;
    }
    float c = c0[hc];    // meaningful for g==0 threads
    unsigned phase = 0;
    for (int t=0; t<MV; t++){
        const float* hsrc = g_h[t & 1];
        // stage h(t) from L2
        #pragma unroll
        for (int i=0;i<8;i++){
            int q = tid + i*256;           // float4 index, 0..2047
            int bb = q >> 6; int kk = (q & 63)*4;
            float4 v = __ldcg((const float4*)&hsrc[bb*256 + kk]);
            *(float4*)&hs[bb][kk] = v;
        }
        __syncthreads();
        // gate dot: sum_k h[k]*ws[rowL][k]
        ull a0=0ull,a1=0ull,a2=0ull,a3=0ull;
        #pragma unroll
        for (int k=0;k<256;k+=8){
            ulonglong2 h01 = *(const ulonglong2*)&hs[b][k];
            ulonglong2 h23 = *(const ulonglong2*)&hs[b][k+4];
            ulonglong2 w01 = *(const ulonglong2*)&ws[rowL][k];
            ulonglong2 w23 = *(const ulonglong2*)&ws[rowL][k+4];
            a0 = ffma2(h01.x, w01.x, a0); a1 = ffma2(h01.y, w01.y, a1);
            a2 = ffma2(h23.x, w23.x, a2); a3 = ffma2(h23.y, w23.y, a3);
        }
        float2 f0=unpack2(a0), f1=unpack2(a1), f2=unpack2(a2), f3=unpack2(a3);
        float sum = ((f0.x+f0.y)+(f1.x+f1.y)) + ((f2.x+f2.y)+(f3.x+f3.y));
        sum += g_xge[((size_t)t*32 + b)*1024 + n];
        gs[g][hcL][b] = sum;
        __syncthreads();
        if (g == 0){
            float gi = gs[0][hcL][b], gf = gs[1][hcL][b];
            float gg = gs[2][hcL][b], go = gs[3][hcL][b];
            c = sigm(gf)*c + sigm(gi)*tanhf(gg);
            float hv = sigm(go)*tanhf(c);
            g_h[(t+1) & 1][b*256 + hc] = hv;     // write buffer != read buffer: no race
            g_encout[((size_t)t*32 + b)*256 + hc] = 0.5f*hv;
        }
        // grid barrier (monotonic counter)
        __threadfence();
        __syncthreads();
        if (tid == 0){
            unsigned a = atomicAdd(&g_barcnt, 1u) + 1u;
            if (a == (unsigned)ENCBLK*(phase+1u)) g_barflag = phase+1u;
            else { while (g_barflag <= phase) { __nanosleep(64); } }
            __threadfence();
        }
        __syncthreads();
        phase++;
    }
}

// ---------------- decoder pointwise update ----------------
__global__ void dec_update(int t){
    int idx = blockIdx.x*256 + threadIdx.x;   // 4032*256
    int r = idx >> 8; int hc = idx & 255;
    int s = r >> 5; int b = r & 31;
    const float* xg = (t == 0) ? &g_sosxg[(size_t)r*1024]
                               : &g_xgd[((size_t)(s + t)*32 + b)*1024];
    const float* gp = &g_gh[(size_t)r*1024];
    float gi = gp[hc]       + xg[hc];
    float gf = gp[256 + hc] + xg[256 + hc];
    float gg = gp[512 + hc] + xg[512 + hc];
    float go = gp[768 + hc] + xg[768 + hc];
    float cv = (t == 0) ? 0.f : g_decc[idx];
    cv = sigm(gf)*cv + sigm(gi)*tanhf(gg);
    g_decc[idx] = cv;
    float hv = sigm(go)*tanhf(cv);
    g_dech[idx] = hv;
    g_decout[(size_t)t*4032*256 + idx] = hv;
}

// ---------------- target / EOS logits (warp-per-dot) ----------------
__global__ void dots_kernel(const int* __restrict__ x, const float* __restrict__ emb,
                            const float* __restrict__ e2vb){
    int item = blockIdx.x*8 + (threadIdx.x >> 5);   // 0..32255
    int lane = threadIdx.x & 31;
    bool iseos = item >= 16128;
    int id = iseos ? item - 16128 : item;
    int s = id >> 7; int rem = id & 127; int k = rem >> 5; int b = rem & 31;
    int t = iseos ? (k + 1) : k;
    int token;
    if (iseos) token = 3;
    else { int pos = s + 1 + k; token = (pos < MV) ? x[b*MV + pos] : 0; }
    const float* a = g_decout + ((size_t)t*4032 + s*32 + b)*256;
    const float* w = emb + (size_t)token*256;
    int base = lane*8;
    float4 a1 = *(const float4*)&a[base], a2 = *(const float4*)&a[base+4];
    float4 w1 = *(const float4*)&w[base], w2 = *(const float4*)&w[base+4];
    float sum = a1.x*w1.x + a1.y*w1.y + a1.z*w1.z + a1.w*w1.w
              + a2.x*w2.x + a2.y*w2.y + a2.z*w2.z + a2.w*w2.w;
    #pragma unroll
    for (int sft=16; sft; sft>>=1) sum += __shfl_xor_sync(0xffffffffu, sum, sft);
    if (lane == 0){
        float v = sum + e2vb[token];
        if (iseos) g_le[id] = v; else g_lt[id] = v;
    }
}

// ---------------- build per-segment log-probs ----------------
__global__ void build_logpy(){
    int s = blockIdx.x, b = threadIdx.x;  // 126 x 32
    float cum = 0.f;
    float isstart = g_issingle[(s+1)*32 + b];
    for (int k=0;k<4;k++){
        int id = (s*4 + k)*32 + b;
        float tlp = g_lt[id] - g_logZ[k*4032 + s*32 + b];
        int pos = s + 1 + k;
        float segis = (pos < MV) ? g_issingle[pos*32 + b] : 0.f;
        cum += tlp + ((k >= 1) ? segis : 0.f);
        float v = cum + ((k >= 1) ? isstart : 0.f)
                + (g_le[id] - g_logZ[(k+1)*4032 + s*32 + b]);
        bool valid = (s + 1 + k) <= 126;
        g_logpy[id] = valid ? v : NEGBIG;
    }
}

// ---------------- segmental DP + final reduction ----------------
__global__ void dp_final(const int* __restrict__ lengths, float* __restrict__ out){
    int b = threadIdx.x;  // 32 threads
    float ap0 = 0.f, ap1 = NEGBIG, ap2 = NEGBIG, ap3 = NEGBIG;
    int target = lengths[b] - 2;
    float nll = 0.f;
    for (int e=1; e<=126; e++){
        float t0 = ap0 + g_logpy[((e-1)*4 + 0)*32 + b];
        float t1 = (e >= 2) ? ap1 + g_logpy[((e-2)*4 + 1)*32 + b] : -1e30f;
        float t2 = (e >= 3) ? ap2 + g_logpy[((e-3)*4 + 2)*32 + b] : -1e30f;
        float t3 = (e >= 4) ? ap3 + g_logpy[((e-4)*4 + 3)*32 + b] : -1e30f;
        float m = fmaxf(fmaxf(t0,t1), fmaxf(t2,t3));
        float ss = expf(t0-m) + expf(t1-m) + expf(t2-m) + expf(t3-m);
        float ae = m + logf(ss);
        ap3 = ap2; ap2 = ap1; ap1 = ap0; ap0 = ae;
        if (e == target) nll = -ae;
    }
    float sumn = nll;
    int sl = lengths[b];
    #pragma unroll
    for (int sft=16; sft; sft>>=1){
        sumn += __shfl_xor_sync(0xffffffffu, sumn, sft);
        sl   += __shfl_xor_sync(0xffffffffu, sl, sft);
    }
    if (b == 0) out[0] = sumn / (float)(sl - 2*BV);
}

// ---------------- host launcher ----------------
extern "C" void kernel_launch(void* const* d_in, const int* in_sizes, int n_in,
                              void* d_out, int out_size){
    const int*   x     = (const int*)d_in[0];
    const int*   lens  = (const int*)d_in[1];
    const float* emb   = (const float*)d_in[2];
    const float* e2vb  = (const float*)d_in[3];
    const float* eWih  = (const float*)d_in[4];
    const float* eWhh  = (const float*)d_in[5];
    const float* ebih  = (const float*)d_in[6];
    const float* ebhh  = (const float*)d_in[7];
    const float* eh0   = (const float*)d_in[8];
    const float* ec0   = (const float*)d_in[9];
    const float* dWih  = (const float*)d_in[10];
    const float* dWhh  = (const float*)d_in[11];
    const float* dbih  = (const float*)d_in[12];
    const float* dbhh  = (const float*)d_in[13];
    const float* dhtW  = (const float*)d_in[14];
    const float* dhtb  = (const float*)d_in[15];
    const float* sosW  = (const float*)d_in[16];
    const float* sosb  = (const float*)d_in[17];
    float* out = (float*)d_out;

    float *inp, *xge, *xgd, *encout, *sos, *sosxg, *dech, *gh, *decout;
    cudaGetSymbolAddress((void**)&inp,    g_inp);
    cudaGetSymbolAddress((void**)&xge,    g_xge);
    cudaGetSymbolAddress((void**)&xgd,    g_xgd);
    cudaGetSymbolAddress((void**)&encout, g_encout);
    cudaGetSymbolAddress((void**)&sos,    g_sos);
    cudaGetSymbolAddress((void**)&sosxg,  g_sosxg);
    cudaGetSymbolAddress((void**)&dech,   g_dech);
    cudaGetSymbolAddress((void**)&gh,     g_gh);
    cudaGetSymbolAddress((void**)&decout, g_decout);

    embed_kernel<<<4096, 256>>>(x, emb);
    init_state<<<288, 256>>>(eh0, dbih, dbhh);

    // input-gate precomputes (include both biases)
    sgemm_nt<<<dim3(32,16), 256>>>(inp, eWih, ebih, ebhh, xge, 4096, 1024, 0);
    sgemm_nt<<<dim3(32,16), 256>>>(inp, dWih, dbih, dbhh, xgd, 4096, 1024, 0);

    // encoder recurrence — one persistent launch
    enc_persist<<<ENCBLK, 256>>>(eWhh, ec0);

    // sos / dec_h0 / sos input-gates
    sgemm_nt<<<dim3(32,4),  256>>>(encout, sosW, sosb, nullptr, sos,   NBV, 256, 0);
    sgemm_nt<<<dim3(32,4),  256>>>(encout, dhtW, dhtb, nullptr, dech,  NBV, 256, 1);
    sgemm_nt<<<dim3(32,16), 256>>>(sos,    dWih, dbih, dbhh,    sosxg, NBV, 1024, 0);

    // decoder recurrence (5 steps)
    for (int t=0; t<5; t++){
        sgemm_nt<<<dim3(32,16), 256>>>(dech, dWhh, nullptr, nullptr, gh, NBV, 1024, 0);
        dec_update<<<4032, 256>>>(t);
    }

    // fused logits logsumexp
    sgemm_logits<<<dim3(158, NCB), 256>>>(decout, emb, e2vb);
    reduce_logz<<<2520, 256>>>();
    dots_kernel<<<4032, 256>>>(x, emb, e2vb);
    build_logpy<<<126, 32>>>();
    dp_final<<<1, 32>>>(lens, out);
}